// round 1
// baseline (speedup 1.0000x reference)
#include <cuda_runtime.h>
#include <math.h>

#define T_TOKENS 2048
#define HID 2048
#define NEXP 32
#define TOPK 8
#define INTER_SZ 768
#define NGU 1536
#define THRESH 0.8f

// ---------------- scratch (static device globals; no allocation) -------------
__device__ int   g_count[NEXP];                       // tokens per expert
__device__ int   g_tokens[NEXP][T_TOKENS];            // token id per (expert, slot)
__device__ int   g_tok_nkeep[T_TOKENS];
__device__ int   g_tok_expert[T_TOKENS][TOPK];
__device__ int   g_tok_slot[T_TOKENS][TOPK];
__device__ float g_tok_w[T_TOKENS][TOPK];
__device__ float g_inter[NEXP][T_TOKENS][INTER_SZ];   // SwiGLU output, ~201MB
__device__ float g_downbuf[(size_t)NEXP * T_TOKENS * HID]; // down output, ~536MB

// ---------------- kernel 0: zero counts -------------------------------------
__global__ void zero_counts_kernel() {
    if (threadIdx.x < NEXP) g_count[threadIdx.x] = 0;
}

// ---------------- kernel 1: router ------------------------------------------
// 1 block per token, 256 threads. Computes logits (fp32 dot), softmax,
// top-8, top-p prefix keep, renorm, and builds per-expert token lists.
__global__ void router_kernel(const float* __restrict__ x,
                              const float* __restrict__ gw) {
    __shared__ float xs[HID];
    __shared__ float logits[NEXP];
    int t = blockIdx.x;
    const float* xp = x + (size_t)t * HID;
    for (int i = threadIdx.x; i < HID; i += blockDim.x) xs[i] = xp[i];
    __syncthreads();

    int warp = threadIdx.x >> 5, lane = threadIdx.x & 31;
    // 8 warps x 4 experts
    #pragma unroll
    for (int eo = 0; eo < 4; eo++) {
        int e = warp * 4 + eo;
        const float* w = gw + (size_t)e * HID;
        float s = 0.f;
        for (int j = lane; j < HID; j += 32) s += xs[j] * w[j];
        #pragma unroll
        for (int o = 16; o; o >>= 1) s += __shfl_xor_sync(0xffffffffu, s, o);
        if (lane == 0) logits[e] = s;
    }
    __syncthreads();

    if (threadIdx.x == 0) {
        float p[NEXP];
        float mx = -1e30f;
        #pragma unroll
        for (int e = 0; e < NEXP; e++) mx = fmaxf(mx, logits[e]);
        float sum = 0.f;
        #pragma unroll
        for (int e = 0; e < NEXP; e++) { p[e] = expf(logits[e] - mx); sum += p[e]; }
        float inv = 1.f / sum;
        #pragma unroll
        for (int e = 0; e < NEXP; e++) p[e] *= inv;

        // top-8 (sorted descending, ties -> lowest index, matching lax.top_k)
        float tv[TOPK]; int ti[TOPK];
        #pragma unroll
        for (int k = 0; k < TOPK; k++) {
            float best = -1.f; int bi = 0;
            #pragma unroll
            for (int e = 0; e < NEXP; e++)
                if (p[e] > best) { best = p[e]; bi = e; }
            tv[k] = best; ti[k] = bi; p[bi] = -1.f;
        }
        // top-p prefix keep on renormed values
        float s8 = 0.f;
        #pragma unroll
        for (int k = 0; k < TOPK; k++) s8 += tv[k];
        float invs8 = 1.f / fmaxf(s8, 1e-12f);
        float cum = 0.f; int cnt_lt = 0;
        #pragma unroll
        for (int k = 0; k < TOPK; k++) {
            cum += tv[k] * invs8;
            if (cum < THRESH) cnt_lt++;
        }
        int keep = min(cnt_lt + 1, TOPK);
        float ssel = 0.f;
        for (int k = 0; k < keep; k++) ssel += tv[k];
        float invsel = 1.f / fmaxf(ssel, 1e-12f);
        g_tok_nkeep[t] = keep;
        for (int k = 0; k < keep; k++) {
            int e = ti[k];
            int slot = atomicAdd(&g_count[e], 1);
            g_tokens[e][slot]   = t;
            g_tok_expert[t][k]  = e;
            g_tok_slot[t][k]    = slot;
            g_tok_w[t][k]       = tv[k] * invsel;
        }
    }
}

// ---------------- kernel 2: grouped gate_up GEMM + SwiGLU -------------------
// grid = (I/BN, T/BM, E). Block computes a [BM x BN] tile of h = silu(g)*u
// for expert z, gathering token rows. Early-exits when m-tile beyond count.
#define BM 64
#define BN 64
#define BK 16

__global__ void gateup_kernel(const float* __restrict__ x,
                              const float* __restrict__ w_gu) {
    int e = blockIdx.z;
    int cnt = g_count[e];
    int m0 = blockIdx.y * BM;
    if (m0 >= cnt) return;
    int n0 = blockIdx.x * BN;

    __shared__ float Xs[BK][BM + 4];
    __shared__ float Gs[BK][BN + 4];
    __shared__ float Us[BK][BN + 4];
    __shared__ int toks[BM];

    int tid = threadIdx.x;
    if (tid < BM) {
        int r = m0 + tid;
        toks[tid] = (r < cnt) ? g_tokens[e][r] : g_tokens[e][0];
    }
    __syncthreads();

    const float* Wg = w_gu + ((size_t)e * NGU + n0) * HID;
    const float* Wu = w_gu + ((size_t)e * NGU + INTER_SZ + n0) * HID;

    float accg[4][4] = {}, accu[4][4] = {};
    int ty = tid >> 4, tx = tid & 15;
    int row0 = ty * 4, col0 = tx * 4;

    for (int k0 = 0; k0 < HID; k0 += BK) {
        #pragma unroll
        for (int i = 0; i < 4; i++) {
            int idx = tid + i * 256;   // 0..1023
            int r  = idx >> 4;
            int kk = idx & 15;
            Xs[kk][r] = x[(size_t)toks[r] * HID + k0 + kk];
            Gs[kk][r] = Wg[(size_t)r * HID + k0 + kk];
            Us[kk][r] = Wu[(size_t)r * HID + k0 + kk];
        }
        __syncthreads();
        #pragma unroll
        for (int k = 0; k < BK; k++) {
            float a[4], bg[4], bu[4];
            #pragma unroll
            for (int i = 0; i < 4; i++) a[i] = Xs[k][row0 + i];
            #pragma unroll
            for (int j = 0; j < 4; j++) { bg[j] = Gs[k][col0 + j]; bu[j] = Us[k][col0 + j]; }
            #pragma unroll
            for (int i = 0; i < 4; i++)
                #pragma unroll
                for (int j = 0; j < 4; j++) {
                    accg[i][j] += a[i] * bg[j];
                    accu[i][j] += a[i] * bu[j];
                }
        }
        __syncthreads();
    }
    #pragma unroll
    for (int i = 0; i < 4; i++) {
        int r = m0 + row0 + i;
        if (r >= cnt) continue;
        float* dst = &g_inter[e][r][n0 + col0];
        #pragma unroll
        for (int j = 0; j < 4; j++) {
            float g = accg[i][j], u = accu[i][j];
            float h = g * (1.f / (1.f + expf(-g))) * u;   // silu(g)*u
            dst[j] = h;
        }
    }
}

// ---------------- kernel 3: grouped down GEMM -------------------------------
// grid = (H/BN, T/BM, E). out_pair[m][n] = sum_k inter[m][k] * Wd[n][k]
__global__ void down_kernel(const float* __restrict__ w_d) {
    int e = blockIdx.z;
    int cnt = g_count[e];
    int m0 = blockIdx.y * BM;
    if (m0 >= cnt) return;
    int n0 = blockIdx.x * BN;

    __shared__ float As[BK][BM + 4];
    __shared__ float Bs[BK][BN + 4];

    int tid = threadIdx.x;
    const float* A = &g_inter[e][0][0];
    const float* W = w_d + (size_t)e * HID * INTER_SZ + (size_t)n0 * INTER_SZ;

    float acc[4][4] = {};
    int ty = tid >> 4, tx = tid & 15;
    int row0 = ty * 4, col0 = tx * 4;

    for (int k0 = 0; k0 < INTER_SZ; k0 += BK) {
        #pragma unroll
        for (int i = 0; i < 4; i++) {
            int idx = tid + i * 256;
            int r  = idx >> 4;
            int kk = idx & 15;
            As[kk][r] = A[(size_t)(m0 + r) * INTER_SZ + k0 + kk];
            Bs[kk][r] = W[(size_t)r * INTER_SZ + k0 + kk];
        }
        __syncthreads();
        #pragma unroll
        for (int k = 0; k < BK; k++) {
            float a[4], b[4];
            #pragma unroll
            for (int i = 0; i < 4; i++) a[i] = As[k][row0 + i];
            #pragma unroll
            for (int j = 0; j < 4; j++) b[j] = Bs[k][col0 + j];
            #pragma unroll
            for (int i = 0; i < 4; i++)
                #pragma unroll
                for (int j = 0; j < 4; j++) acc[i][j] += a[i] * b[j];
        }
        __syncthreads();
    }
    #pragma unroll
    for (int i = 0; i < 4; i++) {
        int r = m0 + row0 + i;
        if (r >= cnt) continue;
        float* dst = &g_downbuf[((size_t)e * T_TOKENS + r) * HID + n0 + col0];
        #pragma unroll
        for (int j = 0; j < 4; j++) dst[j] = acc[i][j];
    }
}

// ---------------- kernel 4: deterministic per-token combine -----------------
__global__ void combine_kernel(float* __restrict__ out) {
    int t = blockIdx.x;
    int nk = g_tok_nkeep[t];
    int   es[TOPK], ss[TOPK];
    float ws[TOPK];
    for (int k = 0; k < nk; k++) {
        es[k] = g_tok_expert[t][k];
        ss[k] = g_tok_slot[t][k];
        ws[k] = g_tok_w[t][k];
    }
    for (int h = threadIdx.x; h < HID; h += blockDim.x) {
        float acc = 0.f;
        for (int k = 0; k < nk; k++)
            acc += ws[k] * g_downbuf[((size_t)es[k] * T_TOKENS + ss[k]) * HID + h];
        out[(size_t)t * HID + h] = acc;
    }
}

// ---------------- launch ----------------------------------------------------
extern "C" void kernel_launch(void* const* d_in, const int* in_sizes, int n_in,
                              void* d_out, int out_size) {
    const float* hidden  = (const float*)d_in[0];   // [2,1024,2048]
    const float* gate_w  = (const float*)d_in[1];   // [32,2048]
    const float* gate_up = (const float*)d_in[2];   // [32,1536,2048]
    const float* down_w  = (const float*)d_in[3];   // [32,2048,768]
    float* out = (float*)d_out;                     // [2,1024,2048]

    zero_counts_kernel<<<1, 32>>>();
    router_kernel<<<T_TOKENS, 256>>>(hidden, gate_w);
    {
        dim3 grid(INTER_SZ / BN, T_TOKENS / BM, NEXP);   // (12, 32, 32)
        gateup_kernel<<<grid, 256>>>(hidden, gate_up);
    }
    {
        dim3 grid(HID / BN, T_TOKENS / BM, NEXP);        // (32, 32, 32)
        down_kernel<<<grid, 256>>>(down_w);
    }
    combine_kernel<<<T_TOKENS, 256>>>(out);
}

// round 3
// speedup vs baseline: 3.4966x; 3.4966x over previous
#include <cuda_runtime.h>
#include <math.h>
#include <stdint.h>

#define T_TOKENS 2048
#define HID 2048
#define NEXP 32
#define TOPK 8
#define INTER_SZ 768
#define NGU 1536
#define THRESH 0.8f

#define BM 128
#define BN 128
#define TK 32
#define ROWF 36   // padded floats per smem row (32 + 4)

// ---------------- scratch (static device globals; no allocation) -------------
__device__ int   g_count[NEXP];
__device__ int   g_tokens[NEXP][T_TOKENS];
__device__ int   g_tok_nkeep[T_TOKENS];
__device__ int   g_tok_expert[T_TOKENS][TOPK];
__device__ int   g_tok_slot[T_TOKENS][TOPK];
__device__ float g_tok_w[T_TOKENS][TOPK];
__device__ __align__(128) float g_h[NEXP][T_TOKENS][INTER_SZ];        // silu(g)*u, ~201MB
__device__ __align__(128) float g_downbuf[(size_t)NEXP * T_TOKENS * HID]; // ~536MB

// ---------------- helpers ----------------------------------------------------
__device__ __forceinline__ uint32_t smem_u32(const void* p) {
    uint32_t a;
    asm("{ .reg .u64 t; cvta.to.shared.u64 t, %1; cvt.u32.u64 %0, t; }" : "=r"(a) : "l"(p));
    return a;
}
__device__ __forceinline__ uint32_t cvt_tf32(float f) {
    uint32_t r;
    asm("cvt.rna.tf32.f32 %0, %1;" : "=r"(r) : "f"(f));
    return r;
}
__device__ __forceinline__ void cpasync16(uint32_t dst, const void* src) {
    asm volatile("cp.async.cg.shared.global [%0], [%1], 16;" :: "r"(dst), "l"(src));
}
__device__ __forceinline__ void mma8(float* d, const uint32_t* a, const uint32_t* b) {
    asm volatile(
        "mma.sync.aligned.m16n8k8.row.col.f32.tf32.tf32.f32 "
        "{%0,%1,%2,%3}, {%4,%5,%6,%7}, {%8,%9}, {%0,%1,%2,%3};"
        : "+f"(d[0]), "+f"(d[1]), "+f"(d[2]), "+f"(d[3])
        : "r"(a[0]), "r"(a[1]), "r"(a[2]), "r"(a[3]), "r"(b[0]), "r"(b[1]));
}
__device__ __forceinline__ float silu(float g) {
    return g * (1.f / (1.f + __expf(-g)));
}

// ---------------- kernel 0: zero counts -------------------------------------
__global__ void zero_counts_kernel() {
    if (threadIdx.x < NEXP) g_count[threadIdx.x] = 0;
}

// ---------------- kernel 1: router ------------------------------------------
__global__ void router_kernel(const float* __restrict__ x,
                              const float* __restrict__ gw) {
    __shared__ float xs[HID];
    __shared__ float logits[NEXP];
    int t = blockIdx.x;
    const float* xp = x + (size_t)t * HID;
    for (int i = threadIdx.x; i < HID; i += blockDim.x) xs[i] = xp[i];
    __syncthreads();

    int warp = threadIdx.x >> 5, lane = threadIdx.x & 31;
    #pragma unroll
    for (int eo = 0; eo < 4; eo++) {
        int e = warp * 4 + eo;
        const float* w = gw + (size_t)e * HID;
        float s = 0.f;
        for (int j = lane; j < HID; j += 32) s += xs[j] * w[j];
        #pragma unroll
        for (int o = 16; o; o >>= 1) s += __shfl_xor_sync(0xffffffffu, s, o);
        if (lane == 0) logits[e] = s;
    }
    __syncthreads();

    if (threadIdx.x == 0) {
        float p[NEXP];
        float mx = -1e30f;
        #pragma unroll
        for (int e = 0; e < NEXP; e++) mx = fmaxf(mx, logits[e]);
        float sum = 0.f;
        #pragma unroll
        for (int e = 0; e < NEXP; e++) { p[e] = expf(logits[e] - mx); sum += p[e]; }
        float inv = 1.f / sum;
        #pragma unroll
        for (int e = 0; e < NEXP; e++) p[e] *= inv;

        float tv[TOPK]; int ti[TOPK];
        #pragma unroll
        for (int k = 0; k < TOPK; k++) {
            float best = -1.f; int bi = 0;
            #pragma unroll
            for (int e = 0; e < NEXP; e++)
                if (p[e] > best) { best = p[e]; bi = e; }
            tv[k] = best; ti[k] = bi; p[bi] = -1.f;
        }
        float s8 = 0.f;
        #pragma unroll
        for (int k = 0; k < TOPK; k++) s8 += tv[k];
        float invs8 = 1.f / fmaxf(s8, 1e-12f);
        float cum = 0.f; int cnt_lt = 0;
        #pragma unroll
        for (int k = 0; k < TOPK; k++) {
            cum += tv[k] * invs8;
            if (cum < THRESH) cnt_lt++;
        }
        int keep = min(cnt_lt + 1, TOPK);
        float ssel = 0.f;
        for (int k = 0; k < keep; k++) ssel += tv[k];
        float invsel = 1.f / fmaxf(ssel, 1e-12f);
        g_tok_nkeep[t] = keep;
        for (int k = 0; k < keep; k++) {
            int e = ti[k];
            int slot = atomicAdd(&g_count[e], 1);
            g_tokens[e][slot]   = t;
            g_tok_expert[t][k]  = e;
            g_tok_slot[t][k]    = slot;
            g_tok_w[t][k]       = tv[k] * invsel;
        }
    }
}

// ---------------- mma.sync tf32 grouped GEMM ---------------------------------
// FUSED=true : A = gathered hidden rows (K=2048), Bg/Bu = gate/up weights,
//              writes h = silu(g)*u to g_h[e].  N covers INTER (768).
// FUSED=false: A = g_h[e] rows (K=768), B = down weights, writes g_downbuf.
template<bool FUSED>
__global__ __launch_bounds__(256, 1)
void moe_mma(const float* __restrict__ X, const float* __restrict__ W) {
    constexpr int KDIM = FUSED ? HID : INTER_SZ;
    constexpr int NS   = KDIM / TK;          // 64 or 24 stages

    const int e   = blockIdx.z;
    const int cnt = g_count[e];
    const int m0  = blockIdx.y * BM;
    if (m0 >= cnt) return;
    const int n0  = blockIdx.x * BN;

    extern __shared__ float smf[];
    float* As = smf;                              // [2][128][ROWF]
    float* B0 = smf + 2 * BM * ROWF;              // [2][128][ROWF]
    float* B1 = smf + 4 * BM * ROWF;              // [2][128][ROWF] (FUSED)
    int*  toks = (int*)(smf + (FUSED ? 6 : 4) * BM * ROWF);

    const int tid  = threadIdx.x;
    const int lane = tid & 31, wid = tid >> 5;
    const int warp_m = wid & 1, warp_n = wid >> 1;

    if (FUSED && tid < BM) {
        int r = m0 + tid;
        toks[tid] = (r < cnt) ? g_tokens[e][r] : g_tokens[e][0];
    }
    __syncthreads();

    const uint32_t sa  = smem_u32(smf);
    const uint32_t aAs = sa;
    const uint32_t aB0 = sa + 2 * BM * ROWF * 4;
    const uint32_t aB1 = sa + 4 * BM * ROWF * 4;

    const float* Wb = W + (size_t)e * (FUSED ? (size_t)NGU * HID : (size_t)HID * INTER_SZ)
                        + (size_t)n0 * KDIM;
    const float* Wu = FUSED ? (W + (size_t)e * NGU * HID + (size_t)(INTER_SZ + n0) * HID)
                            : (const float*)nullptr;

    auto issue = [&](int s) {
        const int buf = s & 1;
        const int k0  = s * TK;
        const uint32_t bufA = aAs + buf * BM * ROWF * 4;
        #pragma unroll
        for (int i = 0; i < 4; i++) {
            int c = tid + i * 256; int row = c >> 3, q = c & 7;
            const float* src;
            if (FUSED) {
                src = X + (size_t)toks[row] * HID + k0 + q * 4;
            } else {
                int r = m0 + row; if (r >= cnt) r = m0;
                src = &g_h[e][r][k0 + q * 4];
            }
            cpasync16(bufA + (row * ROWF + q * 4) * 4, src);
        }
        const uint32_t bufB0 = aB0 + buf * BM * ROWF * 4;
        #pragma unroll
        for (int i = 0; i < 4; i++) {
            int c = tid + i * 256; int row = c >> 3, q = c & 7;
            cpasync16(bufB0 + (row * ROWF + q * 4) * 4, Wb + (size_t)row * KDIM + k0 + q * 4);
        }
        if (FUSED) {
            const uint32_t bufB1 = aB1 + buf * BM * ROWF * 4;
            #pragma unroll
            for (int i = 0; i < 4; i++) {
                int c = tid + i * 256; int row = c >> 3, q = c & 7;
                cpasync16(bufB1 + (row * ROWF + q * 4) * 4, Wu + (size_t)row * KDIM + k0 + q * 4);
            }
        }
        asm volatile("cp.async.commit_group;" ::: "memory");
    };

    float acc0[4][4][4] = {};
    float acc1[4][4][4] = {};

    issue(0);
    issue(1);

    for (int s = 0; s < NS; s++) {
        if (s + 1 < NS) asm volatile("cp.async.wait_group 1;" ::: "memory");
        else            asm volatile("cp.async.wait_group 0;" ::: "memory");
        __syncthreads();

        const float* Af  = As + (s & 1) * BM * ROWF;
        const float* Bf0 = B0 + (s & 1) * BM * ROWF;
        const float* Bf1 = B1 + (s & 1) * BM * ROWF;

        #pragma unroll
        for (int kk = 0; kk < 4; kk++) {
            uint32_t a[4][4], b0[4][2], b1[4][2];
            #pragma unroll
            for (int i = 0; i < 4; i++) {
                const float* p = Af + (warp_m * 64 + i * 16 + (lane >> 2)) * ROWF
                                    + kk * 8 + (lane & 3);
                a[i][0] = cvt_tf32(p[0]);
                a[i][1] = cvt_tf32(p[8 * ROWF]);
                a[i][2] = cvt_tf32(p[4]);
                a[i][3] = cvt_tf32(p[8 * ROWF + 4]);
            }
            #pragma unroll
            for (int j = 0; j < 4; j++) {
                const float* p = Bf0 + (warp_n * 32 + j * 8 + (lane >> 2)) * ROWF
                                     + kk * 8 + (lane & 3);
                b0[j][0] = cvt_tf32(p[0]);
                b0[j][1] = cvt_tf32(p[4]);
                if (FUSED) {
                    const float* q = Bf1 + (warp_n * 32 + j * 8 + (lane >> 2)) * ROWF
                                         + kk * 8 + (lane & 3);
                    b1[j][0] = cvt_tf32(q[0]);
                    b1[j][1] = cvt_tf32(q[4]);
                }
            }
            #pragma unroll
            for (int i = 0; i < 4; i++)
                #pragma unroll
                for (int j = 0; j < 4; j++) {
                    mma8(acc0[i][j], a[i], b0[j]);
                    if (FUSED) mma8(acc1[i][j], a[i], b1[j]);
                }
        }
        __syncthreads();
        if (s + 2 < NS) issue(s + 2);
    }

    // ---- epilogue ----
    #pragma unroll
    for (int i = 0; i < 4; i++) {
        int r0  = m0 + warp_m * 64 + i * 16 + (lane >> 2);
        #pragma unroll
        for (int j = 0; j < 4; j++) {
            int col = n0 + warp_n * 32 + j * 8 + 2 * (lane & 3);
            if (FUSED) {
                if (r0 < cnt) {
                    float2 v = make_float2(silu(acc0[i][j][0]) * acc1[i][j][0],
                                           silu(acc0[i][j][1]) * acc1[i][j][1]);
                    *(float2*)&g_h[e][r0][col] = v;
                }
                if (r0 + 8 < cnt) {
                    float2 v = make_float2(silu(acc0[i][j][2]) * acc1[i][j][2],
                                           silu(acc0[i][j][3]) * acc1[i][j][3]);
                    *(float2*)&g_h[e][r0 + 8][col] = v;
                }
            } else {
                if (r0 < cnt) {
                    float2 v = make_float2(acc0[i][j][0], acc0[i][j][1]);
                    *(float2*)&g_downbuf[((size_t)e * T_TOKENS + r0) * HID + col] = v;
                }
                if (r0 + 8 < cnt) {
                    float2 v = make_float2(acc0[i][j][2], acc0[i][j][3]);
                    *(float2*)&g_downbuf[((size_t)e * T_TOKENS + r0 + 8) * HID + col] = v;
                }
            }
        }
    }
}

// ---------------- kernel 4: deterministic per-token combine -----------------
__global__ void combine_kernel(float* __restrict__ out) {
    int t = blockIdx.x;
    int nk = g_tok_nkeep[t];
    int   es[TOPK], ss[TOPK];
    float ws[TOPK];
    for (int k = 0; k < nk; k++) {
        es[k] = g_tok_expert[t][k];
        ss[k] = g_tok_slot[t][k];
        ws[k] = g_tok_w[t][k];
    }
    for (int h = threadIdx.x; h < HID; h += blockDim.x) {
        float acc = 0.f;
        for (int k = 0; k < nk; k++)
            acc += ws[k] * g_downbuf[((size_t)es[k] * T_TOKENS + ss[k]) * HID + h];
        out[(size_t)t * HID + h] = acc;
    }
}

// ---------------- launch ----------------------------------------------------
#define SMEM_GU   ((6 * BM * ROWF + BM) * 4)   // 111104 B
#define SMEM_DOWN ((4 * BM * ROWF + BM) * 4)   //  74240 B

extern "C" void kernel_launch(void* const* d_in, const int* in_sizes, int n_in,
                              void* d_out, int out_size) {
    const float* hidden  = (const float*)d_in[0];   // [2,1024,2048]
    const float* gate_w  = (const float*)d_in[1];   // [32,2048]
    const float* gate_up = (const float*)d_in[2];   // [32,1536,2048]
    const float* down_w  = (const float*)d_in[3];   // [32,2048,768]
    float* out = (float*)d_out;

    static int configured = 0;
    cudaFuncSetAttribute(moe_mma<true>,  cudaFuncAttributeMaxDynamicSharedMemorySize, SMEM_GU);
    cudaFuncSetAttribute(moe_mma<false>, cudaFuncAttributeMaxDynamicSharedMemorySize, SMEM_DOWN);
    (void)configured;

    zero_counts_kernel<<<1, 32>>>();
    router_kernel<<<T_TOKENS, 256>>>(hidden, gate_w);
    {
        dim3 grid(INTER_SZ / BN, T_TOKENS / BM, NEXP);   // (6, 16, 32)
        moe_mma<true><<<grid, 256, SMEM_GU>>>(hidden, gate_up);
    }
    {
        dim3 grid(HID / BN, T_TOKENS / BM, NEXP);        // (16, 16, 32)
        moe_mma<false><<<grid, 256, SMEM_DOWN>>>(nullptr, down_w);
    }
    combine_kernel<<<T_TOKENS, 256>>>(out);
}